// round 8
// baseline (speedup 1.0000x reference)
#include <cuda_runtime.h>
#include <cuda_bf16.h>
#include <cstdint>

// ---------------------------------------------------------------------------
// SimCLR (NT-Xent) loss, B=4096, D=128, T=0.1 — symmetric triangular GEMM.
// Persistent warp-specialized kernel: 8 MMA warps produce C tiles (bf16,
// pre-scaled) into smem; 4 epilogue warps do exp + row/col sums concurrently.
// ---------------------------------------------------------------------------

#define BROWS    4096
#define TWOB     8192
#define DDIM     128
#define NTILES   64
#define NBLOCKS  (NTILES * (NTILES + 1) / 2)   // 2080
#define TILE_BYTES 32768                       // one 128x128 bf16 tile (2 slabs)
#define SLAB_BYTES 16384
#define BUF_BYTES  65536                       // A+B pair slot
#define C_OFF      131072                      // after 2 slots
#define CSTRIDE_W  76                          // C row stride, 32-bit words (152 bf16)
#define SMEM_DYN   (C_OFF + 128 * CSTRIDE_W * 4)  // 169984
#define GRID_GEMM  148
#define EXP_SCALE 14.4269504089f               // 10 * log2(e)

#define BAR_FULL 1
#define BAR_FREE 2
#define BAR_EPI  3

__device__ __nv_bfloat16 g_zb[TWOB * DDIM];    // swizzled tile layout
__device__ float         g_zf[TWOB * DDIM];    // row-major fp32 (positives)
__device__ float         g_partial[TWOB * NTILES];  // [row][tile]
__device__ float         g_ploss[32];
__device__ float         g_possum[32];

// ---------------------------------------------------------------------------
__device__ __forceinline__ float ex2f(float x) {
    float y;
    asm("ex2.approx.ftz.f32 %0, %1;" : "=f"(y) : "f"(x));
    return y;
}

__device__ __forceinline__ void mma16816(float& c0, float& c1, float& c2, float& c3,
                                         uint32_t a0, uint32_t a1, uint32_t a2, uint32_t a3,
                                         uint32_t b0, uint32_t b1) {
    asm volatile(
        "mma.sync.aligned.m16n8k16.row.col.f32.bf16.bf16.f32 "
        "{%0,%1,%2,%3}, {%4,%5,%6,%7}, {%8,%9}, {%0,%1,%2,%3};"
        : "+f"(c0), "+f"(c1), "+f"(c2), "+f"(c3)
        : "r"(a0), "r"(a1), "r"(a2), "r"(a3), "r"(b0), "r"(b1));
}

__device__ __forceinline__ void ldsm_x4(uint32_t& r0, uint32_t& r1, uint32_t& r2, uint32_t& r3,
                                        uint32_t saddr) {
    asm volatile("ldmatrix.sync.aligned.m8n8.x4.shared.b16 {%0,%1,%2,%3}, [%4];"
                 : "=r"(r0), "=r"(r1), "=r"(r2), "=r"(r3) : "r"(saddr));
}

__device__ __forceinline__ void sts32(uint32_t a, uint32_t v) {
    asm volatile("st.shared.b32 [%0], %1;" :: "r"(a), "r"(v) : "memory");
}

__device__ __forceinline__ void lds128(uint32_t a, uint32_t& r0, uint32_t& r1,
                                       uint32_t& r2, uint32_t& r3) {
    asm volatile("ld.shared.v4.b32 {%0,%1,%2,%3}, [%4];"
                 : "=r"(r0), "=r"(r1), "=r"(r2), "=r"(r3) : "r"(a));
}

#define BAR_SYNC(id, cnt)   asm volatile("bar.sync %0, %1;"   :: "r"(id), "r"(cnt) : "memory")
#define BAR_ARRIVE(id, cnt) asm volatile("bar.arrive %0, %1;" :: "r"(id), "r"(cnt) : "memory")

#define MBAR_WAIT(m, ph) do {                                                  \
    uint32_t _done;                                                            \
    asm volatile("{\n\t.reg .pred p;\n\t"                                      \
        "mbarrier.try_wait.parity.acquire.cta.shared::cta.b64 p, [%1], %2;\n\t"\
        "selp.b32 %0, 1, 0, p;\n\t}"                                           \
        : "=r"(_done) : "r"(m), "r"(ph) : "memory");                           \
    if (!_done) {                                                              \
        asm volatile("{\n\t.reg .pred P1;\n\t"                                 \
        "WL_%=:\n\t"                                                           \
        "mbarrier.try_wait.parity.acquire.cta.shared::cta.b64 P1, [%0], %1, 0x989680;\n\t" \
        "@P1 bra.uni WD_%=;\n\t"                                               \
        "bra.uni WL_%=;\n\t"                                                   \
        "WD_%=:\n\t}" :: "r"(m), "r"(ph) : "memory");                          \
    }                                                                          \
} while (0)

__device__ __forceinline__ void decode_tile(int idx, int& rt, int& ct) {
    int rem = idx, r = 0;
    while (rem >= NTILES - r) { rem -= NTILES - r; r++; }
    rt = r; ct = r + rem;
}

__device__ __forceinline__ void issue_tile_copy(uint32_t dstA, uint32_t mbar, int rt, int ct) {
    const bool diag = (rt == ct);
    uint32_t bytes = diag ? 32768u : 65536u;
    asm volatile("mbarrier.arrive.expect_tx.shared.b64 _, [%0], %1;"
                 :: "r"(mbar), "r"(bytes) : "memory");
    const char* srcA = reinterpret_cast<const char*>(g_zb) + (size_t)rt * TILE_BYTES;
    asm volatile("cp.async.bulk.shared::cta.global.mbarrier::complete_tx::bytes "
                 "[%0], [%1], %2, [%3];"
                 :: "r"(dstA), "l"(srcA), "r"((uint32_t)TILE_BYTES), "r"(mbar) : "memory");
    if (!diag) {
        const char* srcB = reinterpret_cast<const char*>(g_zb) + (size_t)ct * TILE_BYTES;
        asm volatile("cp.async.bulk.shared::cta.global.mbarrier::complete_tx::bytes "
                     "[%0], [%1], %2, [%3];"
                     :: "r"(dstA + (uint32_t)TILE_BYTES), "l"(srcB),
                        "r"((uint32_t)TILE_BYTES), "r"(mbar) : "memory");
    }
}

// ---------------------------------------------------------------------------
// K1: normalize, warp-per-row; write g_zb in tile-local SW128 2-slab layout.
__global__ void k_normalize(const float* __restrict__ xi, const float* __restrict__ xj) {
    int row  = blockIdx.x * 8 + (threadIdx.x >> 5);
    int lane = threadIdx.x & 31;
    const float* src = (row < BROWS) ? (xi + row * DDIM) : (xj + (row - BROWS) * DDIM);
    float4 v = *reinterpret_cast<const float4*>(src + lane * 4);
    float ss = v.x * v.x + v.y * v.y + v.z * v.z + v.w * v.w;
    #pragma unroll
    for (int o = 16; o > 0; o >>= 1) ss += __shfl_xor_sync(0xffffffffu, ss, o);
    float inv = 1.0f / fmaxf(sqrtf(ss), 1e-12f);
    float4 z;
    z.x = v.x * inv; z.y = v.y * inv; z.z = v.z * inv; z.w = v.w * inv;
    *reinterpret_cast<float4*>(g_zf + row * DDIM + lane * 4) = z;

    __nv_bfloat162 b0 = __floats2bfloat162_rn(z.x, z.y);
    __nv_bfloat162 b1 = __floats2bfloat162_rn(z.z, z.w);
    uint2 pk = make_uint2(*reinterpret_cast<uint32_t*>(&b0),
                          *reinterpret_cast<uint32_t*>(&b1));
    char* dst = reinterpret_cast<char*>(g_zb)
              + (row >> 7) * TILE_BYTES + (lane >> 4) * SLAB_BYTES;
    uint32_t wb = (uint32_t)((row & 127) * 128 + (lane & 15) * 8);
    wb ^= (wb >> 3) & 0x70;                       // SW128 swizzle
    *reinterpret_cast<uint2*>(dst + wb) = pk;
}

__global__ void k_nop(void) {}

// ---------------------------------------------------------------------------
// K2: persistent warp-specialized GEMM+exp. 384 thr: warps 0-7 MMA, 8-11 epi.
__global__ __launch_bounds__(384, 1) void k_gemm_exp(void) {
    extern __shared__ char dsm[];
    __shared__ __align__(8) uint64_t s_tmab[2];
    __shared__ float scol[4][128];

    const int tid  = threadIdx.x;
    const int lane = tid & 31;
    const int wid  = tid >> 5;

    const uint32_t dbase = (uint32_t)__cvta_generic_to_shared(dsm);
    const uint32_t cbase = dbase + C_OFF;
    const uint32_t mb0   = (uint32_t)__cvta_generic_to_shared(&s_tmab[0]);

    if (tid == 0) {
        asm volatile("mbarrier.init.shared.b64 [%0], %1;" :: "r"(mb0),     "r"(1u) : "memory");
        asm volatile("mbarrier.init.shared.b64 [%0], %1;" :: "r"(mb0 + 8), "r"(1u) : "memory");
    }
    __syncthreads();

    if (wid < 8) {
        // ===================== compute (producer) warps =====================
        const int g  = lane >> 2;        // 0..7
        const int q  = lane & 3;         // 0..3
        const int wr = wid & 3;          // warp m-row
        const int wc = wid >> 2;         // warp n-col
        const int sub = lane >> 3;
        const int li  = lane & 7;
        const int aRow0 = wr * 32 + li + ((sub & 1) << 3);
        const int aK16  = (sub >> 1) << 4;
        const int xA    = (aRow0 & 7) << 4;
        const int bRow0 = wc * 64 + li + ((sub >> 1) << 3);
        const int bK16  = (sub & 1) << 4;
        const int xB    = (bRow0 & 7) << 4;

        if (tid == 0 && blockIdx.x < NBLOCKS) {
            int rt0, ct0; decode_tile(blockIdx.x, rt0, ct0);
            issue_tile_copy(dbase, mb0, rt0, ct0);
        }

        int it = 0;
        for (int idx = blockIdx.x; idx < NBLOCKS; idx += GRID_GEMM, ++it) {
            int rt, ct; decode_tile(idx, rt, ct);
            const bool diag = (rt == ct);
            const int s = it & 1;
            const uint32_t abase = dbase + (uint32_t)s * BUF_BYTES;
            const uint32_t bbase = diag ? abase : (abase + TILE_BYTES);

            if (tid == 0 && idx + GRID_GEMM < NBLOCKS) {
                int rtn, ctn; decode_tile(idx + GRID_GEMM, rtn, ctn);
                issue_tile_copy(dbase + (uint32_t)(s ^ 1) * BUF_BYTES, mb0 + 8u * (s ^ 1), rtn, ctn);
            }

            MBAR_WAIT(mb0 + 8u * s, (uint32_t)((it >> 1) & 1));

            float c[2][8][4];
            #pragma unroll
            for (int mi = 0; mi < 2; mi++)
                #pragma unroll
                for (int ni = 0; ni < 8; ni++)
                    #pragma unroll
                    for (int e = 0; e < 4; e++) c[mi][ni][e] = 0.0f;

            #pragma unroll
            for (int ks = 0; ks < 8; ks++) {
                const uint32_t slab = (uint32_t)(ks >> 2) * SLAB_BYTES;
                const uint32_t kbA  = (uint32_t)(((ks & 3) * 32 + aK16) ^ xA);
                const uint32_t kbB  = (uint32_t)(((ks & 3) * 32 + bK16) ^ xB);
                uint32_t a[2][4];
                ldsm_x4(a[0][0], a[0][1], a[0][2], a[0][3],
                        abase + slab + (uint32_t)aRow0 * 128 + kbA);
                ldsm_x4(a[1][0], a[1][1], a[1][2], a[1][3],
                        abase + slab + (uint32_t)(aRow0 + 16) * 128 + kbA);
                #pragma unroll
                for (int p = 0; p < 4; p++) {
                    uint32_t b00, b01, b10, b11;
                    ldsm_x4(b00, b01, b10, b11,
                            bbase + slab + (uint32_t)(bRow0 + p * 16) * 128 + kbB);
                    #pragma unroll
                    for (int mi = 0; mi < 2; mi++) {
                        mma16816(c[mi][2*p][0],   c[mi][2*p][1],   c[mi][2*p][2],   c[mi][2*p][3],
                                 a[mi][0], a[mi][1], a[mi][2], a[mi][3], b00, b01);
                        mma16816(c[mi][2*p+1][0], c[mi][2*p+1][1], c[mi][2*p+1][2], c[mi][2*p+1][3],
                                 a[mi][0], a[mi][1], a[mi][2], a[mi][3], b10, b11);
                    }
                }
            }

            if (it > 0) BAR_SYNC(BAR_FREE, 384);    // epi done with C of tile it-1

            // store C (bf16, pre-scaled): word = row*76 + wc*32 + ni*4 + q
            #pragma unroll
            for (int mi = 0; mi < 2; mi++) {
                const int crow = wr * 32 + mi * 16 + g;
                #pragma unroll
                for (int ni = 0; ni < 8; ni++) {
                    const uint32_t w0 = (uint32_t)(crow * CSTRIDE_W + wc * 32 + ni * 4 + q);
                    __nv_bfloat162 p0 = __floats2bfloat162_rn(c[mi][ni][0] * EXP_SCALE,
                                                              c[mi][ni][1] * EXP_SCALE);
                    sts32(cbase + w0 * 4, *reinterpret_cast<uint32_t*>(&p0));
                    __nv_bfloat162 p1 = __floats2bfloat162_rn(c[mi][ni][2] * EXP_SCALE,
                                                              c[mi][ni][3] * EXP_SCALE);
                    sts32(cbase + (w0 + 8 * CSTRIDE_W) * 4, *reinterpret_cast<uint32_t*>(&p1));
                }
            }
            BAR_ARRIVE(BAR_FULL, 384);
        }
    } else {
        // ===================== epilogue (consumer) warps ====================
        const int wg = wid - 8;              // 0..3
        const int r  = wg * 32 + lane;       // local row
        const uint32_t rowaddr = cbase + (uint32_t)(r * CSTRIDE_W) * 4;

        for (int idx = blockIdx.x; idx < NBLOCKS; idx += GRID_GEMM) {
            int rt, ct; decode_tile(idx, rt, ct);
            const bool diag = (rt == ct);

            BAR_SYNC(BAR_FULL, 384);         // wait C produced

            float rowsum = 0.0f;
            #pragma unroll
            for (int chunk = 0; chunk < 4; chunk++) {
                float e[32];
                #pragma unroll
                for (int j = 0; j < 4; j++) {
                    uint32_t u0, u1, u2, u3;
                    lds128(rowaddr + (uint32_t)(chunk * 16 + j * 4) * 4, u0, u1, u2, u3);
                    e[8*j+0] = ex2f(__uint_as_float(u0 << 16));
                    e[8*j+1] = ex2f(__uint_as_float(u0 & 0xFFFF0000u));
                    e[8*j+2] = ex2f(__uint_as_float(u1 << 16));
                    e[8*j+3] = ex2f(__uint_as_float(u1 & 0xFFFF0000u));
                    e[8*j+4] = ex2f(__uint_as_float(u2 << 16));
                    e[8*j+5] = ex2f(__uint_as_float(u2 & 0xFFFF0000u));
                    e[8*j+6] = ex2f(__uint_as_float(u3 << 16));
                    e[8*j+7] = ex2f(__uint_as_float(u3 & 0xFFFF0000u));
                }
                if (diag && chunk == wg) e[lane] = 0.0f;  // self-similarity
                #pragma unroll
                for (int k = 0; k < 32; k++) rowsum += e[k];
                // transpose-reduce: lane l ends with colsum[chunk*32+l] in e[0]
                #pragma unroll
                for (int st = 16; st >= 1; st >>= 1) {
                    #pragma unroll
                    for (int i = 0; i < st; i++) {
                        float keep = (lane & st) ? e[i + st] : e[i];
                        float give = (lane & st) ? e[i] : e[i + st];
                        e[i] = keep + __shfl_xor_sync(0xffffffffu, give, st);
                    }
                }
                scol[wg][chunk * 32 + lane] = e[0];
            }
            g_partial[(rt * 128 + r) * NTILES + ct] = rowsum;

            BAR_SYNC(BAR_EPI, 128);          // scol complete across epi warps
            if (!diag) {
                const int cI = tid - 256;    // 0..127
                float v = scol[0][cI] + scol[1][cI] + scol[2][cI] + scol[3][cI];
                g_partial[(ct * 128 + cI) * NTILES + rt] = v;
            }
            if (idx + GRID_GEMM < NBLOCKS) BAR_ARRIVE(BAR_FREE, 384);
        }
    }
}

// ---------------------------------------------------------------------------
// K3: per-row log-sum + per-block positive sums. grid 32 x 256.
__global__ void k_reduce(void) {
    int tid = threadIdx.x;
    int lane = tid & 31, wid = tid >> 5;
    __shared__ float sred1[8], sred2[8];

    int row = blockIdx.x * 256 + tid;
    const float4* p = reinterpret_cast<const float4*>(g_partial + row * NTILES);
    float s = 0.0f;
    #pragma unroll
    for (int i = 0; i < 16; i++) {
        float4 v = p[i];
        s += (v.x + v.y) + (v.z + v.w);
    }
    float lg = logf(s);
    #pragma unroll
    for (int o = 16; o > 0; o >>= 1) lg += __shfl_xor_sync(0xffffffffu, lg, o);
    if (lane == 0) sred1[wid] = lg;

    int pr = blockIdx.x * 128 + (tid >> 1);
    int h  = tid & 1;
    const float4* pa = reinterpret_cast<const float4*>(g_zf + pr * DDIM + h * 64);
    const float4* pb = reinterpret_cast<const float4*>(g_zf + (pr + BROWS) * DDIM + h * 64);
    float d = 0.0f;
    #pragma unroll
    for (int e = 0; e < 16; e++) {
        float4 va = pa[e], vb = pb[e];
        d += va.x * vb.x + va.y * vb.y + va.z * vb.z + va.w * vb.w;
    }
    d += __shfl_xor_sync(0xffffffffu, d, 1);
    float ps = (h == 0) ? d : 0.0f;
    #pragma unroll
    for (int o = 16; o > 0; o >>= 1) ps += __shfl_xor_sync(0xffffffffu, ps, o);
    if (lane == 0) sred2[wid] = ps;

    __syncthreads();
    if (tid == 0) {
        float t1 = 0.0f, t2 = 0.0f;
        #pragma unroll
        for (int i = 0; i < 8; i++) { t1 += sred1[i]; t2 += sred2[i]; }
        g_ploss[blockIdx.x]  = t1;
        g_possum[blockIdx.x] = t2;
    }
}

// ---------------------------------------------------------------------------
// K4: final scalar, single warp: (sum logs - 20 * sum pos) / 8192
__global__ void k_finalize(float* __restrict__ out) {
    int lane = threadIdx.x;
    float acc = g_ploss[lane] - 20.0f * g_possum[lane];
    #pragma unroll
    for (int o = 16; o > 0; o >>= 1) acc += __shfl_xor_sync(0xffffffffu, acc, o);
    if (lane == 0) out[0] = acc / (float)TWOB;
}

// ---------------------------------------------------------------------------
extern "C" void kernel_launch(void* const* d_in, const int* in_sizes, int n_in,
                              void* d_out, int out_size) {
    const float* xi = (const float*)d_in[0];
    const float* xj = (const float*)d_in[1];
    float* out = (float*)d_out;

    k_normalize<<<TWOB / 8, 256>>>(xi, xj);
    k_nop<<<1, 32>>>();
    k_nop<<<1, 32>>>();

    cudaFuncSetAttribute(k_gemm_exp, cudaFuncAttributeMaxDynamicSharedMemorySize, SMEM_DYN);
    k_gemm_exp<<<GRID_GEMM, 384, SMEM_DYN>>>();

    k_reduce<<<32, 256>>>();
    k_finalize<<<1, 32>>>(out);
}

// round 9
// speedup vs baseline: 1.3378x; 1.3378x over previous
#include <cuda_runtime.h>
#include <cuda_bf16.h>
#include <cstdint>

// ---------------------------------------------------------------------------
// SimCLR (NT-Xent) loss, B=4096, D=128, T=0.1 — symmetric triangular GEMM.
// Persistent (2 CTA/SM) version of the R7 kernel: one A/B smem buffer per CTA,
// next tile's cp.async.bulk issued right after mainloop reads complete, so the
// copy overlaps the epilogue. No wave transitions.
// ---------------------------------------------------------------------------

#define BROWS    4096
#define TWOB     8192
#define DDIM     128
#define NTILES   64
#define NBLOCKS  (NTILES * (NTILES + 1) / 2)   // 2080
#define TILE_BYTES 32768                       // 128 rows x 256B (two 16KB slabs)
#define SLAB_BYTES 16384
#define GRID_GEMM  296                         // 2 per SM
#define EXP_SCALE 14.4269504089f               // 10 * log2(e)

__device__ __nv_bfloat16 g_zb[TWOB * DDIM];    // swizzled tile layout
__device__ float         g_zf[TWOB * DDIM];    // row-major fp32 (positives)
__device__ float         g_partial[TWOB * NTILES];  // [row][tile]
__device__ float         g_ploss[32];
__device__ float         g_possum[32];

// ---------------------------------------------------------------------------
__device__ __forceinline__ float ex2f(float x) {
    float y;
    asm("ex2.approx.ftz.f32 %0, %1;" : "=f"(y) : "f"(x));
    return y;
}

__device__ __forceinline__ void mma16816(float& c0, float& c1, float& c2, float& c3,
                                         uint32_t a0, uint32_t a1, uint32_t a2, uint32_t a3,
                                         uint32_t b0, uint32_t b1) {
    asm volatile(
        "mma.sync.aligned.m16n8k16.row.col.f32.bf16.bf16.f32 "
        "{%0,%1,%2,%3}, {%4,%5,%6,%7}, {%8,%9}, {%0,%1,%2,%3};"
        : "+f"(c0), "+f"(c1), "+f"(c2), "+f"(c3)
        : "r"(a0), "r"(a1), "r"(a2), "r"(a3), "r"(b0), "r"(b1));
}

__device__ __forceinline__ void ldsm_x4(uint32_t& r0, uint32_t& r1, uint32_t& r2, uint32_t& r3,
                                        uint32_t saddr) {
    asm volatile("ldmatrix.sync.aligned.m8n8.x4.shared.b16 {%0,%1,%2,%3}, [%4];"
                 : "=r"(r0), "=r"(r1), "=r"(r2), "=r"(r3) : "r"(saddr));
}

#define MBAR_WAIT(m, ph) do {                                                  \
    uint32_t _done;                                                            \
    asm volatile("{\n\t.reg .pred p;\n\t"                                      \
        "mbarrier.try_wait.parity.acquire.cta.shared::cta.b64 p, [%1], %2;\n\t"\
        "selp.b32 %0, 1, 0, p;\n\t}"                                           \
        : "=r"(_done) : "r"(m), "r"(ph) : "memory");                           \
    if (!_done) {                                                              \
        asm volatile("{\n\t.reg .pred P1;\n\t"                                 \
        "WL_%=:\n\t"                                                           \
        "mbarrier.try_wait.parity.acquire.cta.shared::cta.b64 P1, [%0], %1, 0x989680;\n\t" \
        "@P1 bra.uni WD_%=;\n\t"                                               \
        "bra.uni WL_%=;\n\t"                                                   \
        "WD_%=:\n\t}" :: "r"(m), "r"(ph) : "memory");                          \
    }                                                                          \
} while (0)

__device__ __forceinline__ void decode_tile(int idx, int& rt, int& ct) {
    int rem = idx, r = 0;
    while (rem >= NTILES - r) { rem -= NTILES - r; r++; }
    rt = r; ct = r + rem;
}

__device__ __forceinline__ void issue_tile_copy(uint32_t dstA, uint32_t mbar, int rt, int ct) {
    const bool diag = (rt == ct);
    uint32_t bytes = diag ? 32768u : 65536u;
    asm volatile("mbarrier.arrive.expect_tx.shared.b64 _, [%0], %1;"
                 :: "r"(mbar), "r"(bytes) : "memory");
    const char* srcA = reinterpret_cast<const char*>(g_zb) + (size_t)rt * TILE_BYTES;
    asm volatile("cp.async.bulk.shared::cta.global.mbarrier::complete_tx::bytes "
                 "[%0], [%1], %2, [%3];"
                 :: "r"(dstA), "l"(srcA), "r"((uint32_t)TILE_BYTES), "r"(mbar) : "memory");
    if (!diag) {
        const char* srcB = reinterpret_cast<const char*>(g_zb) + (size_t)ct * TILE_BYTES;
        asm volatile("cp.async.bulk.shared::cta.global.mbarrier::complete_tx::bytes "
                     "[%0], [%1], %2, [%3];"
                     :: "r"(dstA + (uint32_t)TILE_BYTES), "l"(srcB),
                        "r"((uint32_t)TILE_BYTES), "r"(mbar) : "memory");
    }
}

// ---------------------------------------------------------------------------
// K1: normalize, warp-per-row; write g_zb in tile-local SW128 2-slab layout.
__global__ void k_normalize(const float* __restrict__ xi, const float* __restrict__ xj) {
    int row  = blockIdx.x * 8 + (threadIdx.x >> 5);
    int lane = threadIdx.x & 31;
    const float* src = (row < BROWS) ? (xi + row * DDIM) : (xj + (row - BROWS) * DDIM);
    float4 v = *reinterpret_cast<const float4*>(src + lane * 4);
    float ss = v.x * v.x + v.y * v.y + v.z * v.z + v.w * v.w;
    #pragma unroll
    for (int o = 16; o > 0; o >>= 1) ss += __shfl_xor_sync(0xffffffffu, ss, o);
    float inv = 1.0f / fmaxf(sqrtf(ss), 1e-12f);
    float4 z;
    z.x = v.x * inv; z.y = v.y * inv; z.z = v.z * inv; z.w = v.w * inv;
    *reinterpret_cast<float4*>(g_zf + row * DDIM + lane * 4) = z;

    __nv_bfloat162 b0 = __floats2bfloat162_rn(z.x, z.y);
    __nv_bfloat162 b1 = __floats2bfloat162_rn(z.z, z.w);
    uint2 pk = make_uint2(*reinterpret_cast<uint32_t*>(&b0),
                          *reinterpret_cast<uint32_t*>(&b1));
    char* dst = reinterpret_cast<char*>(g_zb)
              + (row >> 7) * TILE_BYTES + (lane >> 4) * SLAB_BYTES;
    uint32_t wb = (uint32_t)((row & 127) * 128 + (lane & 15) * 8);
    wb ^= (wb >> 3) & 0x70;                       // SW128 swizzle
    *reinterpret_cast<uint2*>(dst + wb) = pk;
}

// spacer so ncu's capture slot (4th launch) lands on k_gemm_exp
__global__ void k_nop(void) {}

// ---------------------------------------------------------------------------
// K2: persistent triangular fused GEMM + exp + row/col sums.
// 8 warps = 4(m) x 2(n), warp tile 32x64, ldmatrix fragments.
__global__ __launch_bounds__(256, 2) void k_gemm_exp(void) {
    extern __shared__ char dsm[];
    __shared__ __align__(8) uint64_t s_mbar;
    __shared__ float srow[2][128];
    __shared__ float scol[4][128];

    const int tid  = threadIdx.x;
    const int lane = tid & 31;
    const int wid  = tid >> 5;
    const int g    = lane >> 2;
    const int q    = lane & 3;
    const int wr   = wid & 3;        // warp m-row 0..3
    const int wc   = wid >> 2;       // warp n-col 0..1

    const uint32_t dbase = (uint32_t)__cvta_generic_to_shared(dsm);
    const uint32_t abase = (dbase + 1023u) & ~1023u;
    const uint32_t mbar  = (uint32_t)__cvta_generic_to_shared(&s_mbar);

    // ldmatrix lane geometry (validated fragment maps)
    const int sub = lane >> 3;       // 0..3
    const int li  = lane & 7;
    const int aRow0 = wr * 32 + li + ((sub & 1) << 3);
    const int aK16  = (sub >> 1) << 4;            // 0 or 16 bytes
    const int xA    = (aRow0 & 7) << 4;           // swizzle XOR
    const int bRow0 = wc * 64 + li + ((sub >> 1) << 3);
    const int bK16  = (sub & 1) << 4;
    const int xB    = (bRow0 & 7) << 4;

    if (tid == 0)
        asm volatile("mbarrier.init.shared.b64 [%0], %1;" :: "r"(mbar), "r"(1u) : "memory");
    __syncthreads();
    if (tid == 0) {
        int rt0, ct0; decode_tile(blockIdx.x, rt0, ct0);
        issue_tile_copy(abase, mbar, rt0, ct0);
    }

    int it = 0;
    for (int idx = blockIdx.x; idx < NBLOCKS; idx += GRID_GEMM, ++it) {
        int rt, ct; decode_tile(idx, rt, ct);
        const bool diag = (rt == ct);
        const uint32_t bbase = diag ? abase : (abase + TILE_BYTES);

        MBAR_WAIT(mbar, (uint32_t)(it & 1));

        float c[2][8][4];
        #pragma unroll
        for (int mi = 0; mi < 2; mi++)
            #pragma unroll
            for (int ni = 0; ni < 8; ni++)
                #pragma unroll
                for (int e = 0; e < 4; e++) c[mi][ni][e] = 0.0f;

        #pragma unroll
        for (int ks = 0; ks < 8; ks++) {
            const uint32_t slab = (uint32_t)(ks >> 2) * SLAB_BYTES;
            const uint32_t kbA  = (uint32_t)(((ks & 3) * 32 + aK16) ^ xA);
            const uint32_t kbB  = (uint32_t)(((ks & 3) * 32 + bK16) ^ xB);
            uint32_t a[2][4];
            ldsm_x4(a[0][0], a[0][1], a[0][2], a[0][3],
                    abase + slab + (uint32_t)aRow0 * 128 + kbA);
            ldsm_x4(a[1][0], a[1][1], a[1][2], a[1][3],
                    abase + slab + (uint32_t)(aRow0 + 16) * 128 + kbA);
            #pragma unroll
            for (int p = 0; p < 4; p++) {
                uint32_t b00, b01, b10, b11;
                ldsm_x4(b00, b01, b10, b11,
                        bbase + slab + (uint32_t)(bRow0 + p * 16) * 128 + kbB);
                #pragma unroll
                for (int mi = 0; mi < 2; mi++) {
                    mma16816(c[mi][2*p][0],   c[mi][2*p][1],   c[mi][2*p][2],   c[mi][2*p][3],
                             a[mi][0], a[mi][1], a[mi][2], a[mi][3], b00, b01);
                    mma16816(c[mi][2*p+1][0], c[mi][2*p+1][1], c[mi][2*p+1][2], c[mi][2*p+1][3],
                             a[mi][0], a[mi][1], a[mi][2], a[mi][3], b10, b11);
                }
            }
        }

        __syncthreads();                  // all warps done reading A/B
        if (tid == 0 && idx + GRID_GEMM < NBLOCKS) {
            int rtn, ctn; decode_tile(idx + GRID_GEMM, rtn, ctn);
            issue_tile_copy(abase, mbar, rtn, ctn);   // overlaps epilogue
        }

        // ---- epilogue: exp, diag mask, row sums + deferred col butterfly ----
        float rs[2][2];
        rs[0][0] = rs[0][1] = rs[1][0] = rs[1][1] = 0.0f;
        float cs[16];
        #pragma unroll
        for (int v = 0; v < 16; v++) cs[v] = 0.0f;

        #pragma unroll
        for (int ni = 0; ni < 8; ni++) {
            const int lc = wc * 64 + ni * 8 + 2 * q;
            #pragma unroll
            for (int mi = 0; mi < 2; mi++) {
                const int lr0 = wr * 32 + mi * 16 + g;
                const int lr1 = lr0 + 8;
                float v0 = ex2f(c[mi][ni][0] * EXP_SCALE);
                float v1 = ex2f(c[mi][ni][1] * EXP_SCALE);
                float v2 = ex2f(c[mi][ni][2] * EXP_SCALE);
                float v3 = ex2f(c[mi][ni][3] * EXP_SCALE);
                if (diag) {
                    if (lr0 == lc)     v0 = 0.0f;
                    if (lr0 == lc + 1) v1 = 0.0f;
                    if (lr1 == lc)     v2 = 0.0f;
                    if (lr1 == lc + 1) v3 = 0.0f;
                }
                rs[mi][0] += v0 + v1;
                rs[mi][1] += v2 + v3;
                cs[2 * ni]     += v0 + v2;
                cs[2 * ni + 1] += v1 + v3;
            }
        }

        if (!diag) {
            #pragma unroll
            for (int i = 0; i < 8; i++) {
                float keep = (lane & 4) ? cs[i + 8] : cs[i];
                float give = (lane & 4) ? cs[i] : cs[i + 8];
                cs[i] = keep + __shfl_xor_sync(0xffffffffu, give, 4);
            }
            #pragma unroll
            for (int i = 0; i < 4; i++) {
                float keep = (lane & 8) ? cs[i + 4] : cs[i];
                float give = (lane & 8) ? cs[i] : cs[i + 4];
                cs[i] = keep + __shfl_xor_sync(0xffffffffu, give, 8);
            }
            #pragma unroll
            for (int i = 0; i < 2; i++) {
                float keep = (lane & 16) ? cs[i + 2] : cs[i];
                float give = (lane & 16) ? cs[i] : cs[i + 2];
                cs[i] = keep + __shfl_xor_sync(0xffffffffu, give, 16);
            }
            const int v0 = ((lane & 4) ? 8 : 0) + ((lane & 8) ? 4 : 0) + ((lane & 16) ? 2 : 0);
            const int col0 = wc * 64 + (v0 >> 1) * 8 + 2 * q;
            scol[wr][col0]     = cs[0];
            scol[wr][col0 + 1] = cs[1];
        }

        #pragma unroll
        for (int mi = 0; mi < 2; mi++) {
            rs[mi][0] += __shfl_xor_sync(0xffffffffu, rs[mi][0], 1);
            rs[mi][0] += __shfl_xor_sync(0xffffffffu, rs[mi][0], 2);
            rs[mi][1] += __shfl_xor_sync(0xffffffffu, rs[mi][1], 1);
            rs[mi][1] += __shfl_xor_sync(0xffffffffu, rs[mi][1], 2);
        }
        if (q == 0) {
            #pragma unroll
            for (int mi = 0; mi < 2; mi++) {
                const int lr = wr * 32 + mi * 16 + g;
                srow[wc][lr]     = rs[mi][0];
                srow[wc][lr + 8] = rs[mi][1];
            }
        }
        __syncthreads();

        if (tid < 128) {
            float v = srow[0][tid] + srow[1][tid];
            g_partial[(rt * 128 + tid) * NTILES + ct] = v;
        } else if (!diag) {
            const int cI = tid - 128;
            float v = scol[0][cI] + scol[1][cI] + scol[2][cI] + scol[3][cI];
            g_partial[(ct * 128 + cI) * NTILES + rt] = v;
        }
        // next iteration's post-mainloop __syncthreads orders these global
        // writes before scol/srow are overwritten.
    }
}

// ---------------------------------------------------------------------------
// K3: per-row log-sum + per-block positive sums. grid 32 x 256.
__global__ void k_reduce(void) {
    int tid = threadIdx.x;
    int lane = tid & 31, wid = tid >> 5;
    __shared__ float sred1[8], sred2[8];

    int row = blockIdx.x * 256 + tid;
    const float4* p = reinterpret_cast<const float4*>(g_partial + row * NTILES);
    float s = 0.0f;
    #pragma unroll
    for (int i = 0; i < 16; i++) {
        float4 v = p[i];
        s += (v.x + v.y) + (v.z + v.w);
    }
    float lg = logf(s);
    #pragma unroll
    for (int o = 16; o > 0; o >>= 1) lg += __shfl_xor_sync(0xffffffffu, lg, o);
    if (lane == 0) sred1[wid] = lg;

    int pr = blockIdx.x * 128 + (tid >> 1);
    int h  = tid & 1;
    const float4* pa = reinterpret_cast<const float4*>(g_zf + pr * DDIM + h * 64);
    const float4* pb = reinterpret_cast<const float4*>(g_zf + (pr + BROWS) * DDIM + h * 64);
    float d = 0.0f;
    #pragma unroll
    for (int e = 0; e < 16; e++) {
        float4 va = pa[e], vb = pb[e];
        d += va.x * vb.x + va.y * vb.y + va.z * vb.z + va.w * vb.w;
    }
    d += __shfl_xor_sync(0xffffffffu, d, 1);
    float ps = (h == 0) ? d : 0.0f;
    #pragma unroll
    for (int o = 16; o > 0; o >>= 1) ps += __shfl_xor_sync(0xffffffffu, ps, o);
    if (lane == 0) sred2[wid] = ps;

    __syncthreads();
    if (tid == 0) {
        float t1 = 0.0f, t2 = 0.0f;
        #pragma unroll
        for (int i = 0; i < 8; i++) { t1 += sred1[i]; t2 += sred2[i]; }
        g_ploss[blockIdx.x]  = t1;
        g_possum[blockIdx.x] = t2;
    }
}

// ---------------------------------------------------------------------------
// K4: final scalar, single warp: (sum logs - 20 * sum pos) / 8192
__global__ void k_finalize(float* __restrict__ out) {
    int lane = threadIdx.x;
    float acc = g_ploss[lane] - 20.0f * g_possum[lane];
    #pragma unroll
    for (int o = 16; o > 0; o >>= 1) acc += __shfl_xor_sync(0xffffffffu, acc, o);
    if (lane == 0) out[0] = acc / (float)TWOB;
}

// ---------------------------------------------------------------------------
extern "C" void kernel_launch(void* const* d_in, const int* in_sizes, int n_in,
                              void* d_out, int out_size) {
    const float* xi = (const float*)d_in[0];
    const float* xj = (const float*)d_in[1];
    float* out = (float*)d_out;

    k_normalize<<<TWOB / 8, 256>>>(xi, xj);
    k_nop<<<1, 32>>>();
    k_nop<<<1, 32>>>();

    const int smem_bytes = 2 * TILE_BYTES + 1024;   // 66560 -> 2 CTAs/SM
    cudaFuncSetAttribute(k_gemm_exp, cudaFuncAttributeMaxDynamicSharedMemorySize, smem_bytes);
    k_gemm_exp<<<GRID_GEMM, 256, smem_bytes>>>();

    k_reduce<<<32, 256>>>();
    k_finalize<<<1, 32>>>(out);
}

// round 10
// speedup vs baseline: 1.3976x; 1.0447x over previous
#include <cuda_runtime.h>
#include <cuda_bf16.h>
#include <cstdint>

// ---------------------------------------------------------------------------
// SimCLR (NT-Xent) loss, B=4096, D=128, T=0.1 — symmetric triangular GEMM.
// Persistent (2 CTA/SM), software-pipelined mma.sync mainloop, bulk-copy tiles,
// fused exp+row/col-sum epilogue; reduce+finalize fused (last-block pattern).
// ---------------------------------------------------------------------------

#define BROWS    4096
#define TWOB     8192
#define DDIM     128
#define NTILES   64
#define NBLOCKS  (NTILES * (NTILES + 1) / 2)   // 2080
#define TILE_BYTES 32768
#define SLAB_BYTES 16384
#define GRID_GEMM  296                         // 2 per SM
#define EXP_SCALE 14.4269504089f               // 10 * log2(e)

__device__ __nv_bfloat16 g_zb[TWOB * DDIM];    // swizzled tile layout
__device__ float         g_zf[TWOB * DDIM];    // row-major fp32 (positives)
__device__ float         g_partial[TWOB * NTILES];  // [row][tile]
__device__ float         g_ploss[64];
__device__ float         g_possum[64];
__device__ int           g_ctr = 0;

// ---------------------------------------------------------------------------
__device__ __forceinline__ float ex2f(float x) {
    float y;
    asm("ex2.approx.ftz.f32 %0, %1;" : "=f"(y) : "f"(x));
    return y;
}

__device__ __forceinline__ void mma16816(float& c0, float& c1, float& c2, float& c3,
                                         uint32_t a0, uint32_t a1, uint32_t a2, uint32_t a3,
                                         uint32_t b0, uint32_t b1) {
    asm volatile(
        "mma.sync.aligned.m16n8k16.row.col.f32.bf16.bf16.f32 "
        "{%0,%1,%2,%3}, {%4,%5,%6,%7}, {%8,%9}, {%0,%1,%2,%3};"
        : "+f"(c0), "+f"(c1), "+f"(c2), "+f"(c3)
        : "r"(a0), "r"(a1), "r"(a2), "r"(a3), "r"(b0), "r"(b1));
}

__device__ __forceinline__ void ldsm_x4(uint32_t& r0, uint32_t& r1, uint32_t& r2, uint32_t& r3,
                                        uint32_t saddr) {
    asm volatile("ldmatrix.sync.aligned.m8n8.x4.shared.b16 {%0,%1,%2,%3}, [%4];"
                 : "=r"(r0), "=r"(r1), "=r"(r2), "=r"(r3) : "r"(saddr));
}

#define MBAR_WAIT(m, ph) do {                                                  \
    uint32_t _done;                                                            \
    asm volatile("{\n\t.reg .pred p;\n\t"                                      \
        "mbarrier.try_wait.parity.acquire.cta.shared::cta.b64 p, [%1], %2;\n\t"\
        "selp.b32 %0, 1, 0, p;\n\t}"                                           \
        : "=r"(_done) : "r"(m), "r"(ph) : "memory");                           \
    if (!_done) {                                                              \
        asm volatile("{\n\t.reg .pred P1;\n\t"                                 \
        "WL_%=:\n\t"                                                           \
        "mbarrier.try_wait.parity.acquire.cta.shared::cta.b64 P1, [%0], %1, 0x989680;\n\t" \
        "@P1 bra.uni WD_%=;\n\t"                                               \
        "bra.uni WL_%=;\n\t"                                                   \
        "WD_%=:\n\t}" :: "r"(m), "r"(ph) : "memory");                          \
    }                                                                          \
} while (0)

__device__ __forceinline__ void decode_tile(int idx, int& rt, int& ct) {
    int rem = idx, r = 0;
    while (rem >= NTILES - r) { rem -= NTILES - r; r++; }
    rt = r; ct = r + rem;
}

__device__ __forceinline__ void issue_tile_copy(uint32_t dstA, uint32_t mbar, int rt, int ct) {
    const bool diag = (rt == ct);
    uint32_t bytes = diag ? 32768u : 65536u;
    asm volatile("mbarrier.arrive.expect_tx.shared.b64 _, [%0], %1;"
                 :: "r"(mbar), "r"(bytes) : "memory");
    const char* srcA = reinterpret_cast<const char*>(g_zb) + (size_t)rt * TILE_BYTES;
    asm volatile("cp.async.bulk.shared::cta.global.mbarrier::complete_tx::bytes "
                 "[%0], [%1], %2, [%3];"
                 :: "r"(dstA), "l"(srcA), "r"((uint32_t)TILE_BYTES), "r"(mbar) : "memory");
    if (!diag) {
        const char* srcB = reinterpret_cast<const char*>(g_zb) + (size_t)ct * TILE_BYTES;
        asm volatile("cp.async.bulk.shared::cta.global.mbarrier::complete_tx::bytes "
                     "[%0], [%1], %2, [%3];"
                     :: "r"(dstA + (uint32_t)TILE_BYTES), "l"(srcB),
                        "r"((uint32_t)TILE_BYTES), "r"(mbar) : "memory");
    }
}

// ---------------------------------------------------------------------------
// K1: normalize, warp-per-row; write g_zb in tile-local SW128 2-slab layout.
__global__ void k_normalize(const float* __restrict__ xi, const float* __restrict__ xj) {
    int row  = blockIdx.x * 8 + (threadIdx.x >> 5);
    int lane = threadIdx.x & 31;
    const float* src = (row < BROWS) ? (xi + row * DDIM) : (xj + (row - BROWS) * DDIM);
    float4 v = *reinterpret_cast<const float4*>(src + lane * 4);
    float ss = v.x * v.x + v.y * v.y + v.z * v.z + v.w * v.w;
    #pragma unroll
    for (int o = 16; o > 0; o >>= 1) ss += __shfl_xor_sync(0xffffffffu, ss, o);
    float inv = 1.0f / fmaxf(sqrtf(ss), 1e-12f);
    float4 z;
    z.x = v.x * inv; z.y = v.y * inv; z.z = v.z * inv; z.w = v.w * inv;
    *reinterpret_cast<float4*>(g_zf + row * DDIM + lane * 4) = z;

    __nv_bfloat162 b0 = __floats2bfloat162_rn(z.x, z.y);
    __nv_bfloat162 b1 = __floats2bfloat162_rn(z.z, z.w);
    uint2 pk = make_uint2(*reinterpret_cast<uint32_t*>(&b0),
                          *reinterpret_cast<uint32_t*>(&b1));
    char* dst = reinterpret_cast<char*>(g_zb)
              + (row >> 7) * TILE_BYTES + (lane >> 4) * SLAB_BYTES;
    uint32_t wb = (uint32_t)((row & 127) * 128 + (lane & 15) * 8);
    wb ^= (wb >> 3) & 0x70;                       // SW128 swizzle
    *reinterpret_cast<uint2*>(dst + wb) = pk;
}

// ---------------------------------------------------------------------------
// K2: persistent triangular fused GEMM + exp + row/col sums.
// 8 warps = 4(m) x 2(n), warp tile 32x64, software-pipelined ldmatrix.
__global__ __launch_bounds__(256, 2) void k_gemm_exp(void) {
    extern __shared__ char dsm[];
    __shared__ __align__(8) uint64_t s_mbar;
    __shared__ float srow[2][128];
    __shared__ float scol[4][128];

    const int tid  = threadIdx.x;
    const int lane = tid & 31;
    const int wid  = tid >> 5;
    const int g    = lane >> 2;
    const int q    = lane & 3;
    const int wr   = wid & 3;        // warp m-row 0..3
    const int wc   = wid >> 2;       // warp n-col 0..1

    const uint32_t dbase = (uint32_t)__cvta_generic_to_shared(dsm);
    const uint32_t abase = (dbase + 1023u) & ~1023u;
    const uint32_t mbar  = (uint32_t)__cvta_generic_to_shared(&s_mbar);

    // ldmatrix lane geometry (validated fragment maps)
    const int sub = lane >> 3;       // 0..3
    const int li  = lane & 7;
    const int aRow0 = wr * 32 + li + ((sub & 1) << 3);
    const int aK16  = (sub >> 1) << 4;
    const int xA    = (aRow0 & 7) << 4;
    const int bRow0 = wc * 64 + li + ((sub >> 1) << 3);
    const int bK16  = (sub & 1) << 4;
    const int xB    = (bRow0 & 7) << 4;

#define A_AD(ks)     (abase + (uint32_t)(((ks) >> 2) * SLAB_BYTES) + (uint32_t)aRow0 * 128 \
                      + (uint32_t)((((ks) & 3) * 32 + aK16) ^ xA))
#define A_AD2(ks)    (abase + (uint32_t)(((ks) >> 2) * SLAB_BYTES) + (uint32_t)(aRow0 + 16) * 128 \
                      + (uint32_t)((((ks) & 3) * 32 + aK16) ^ xA))
#define B_AD(ks, p)  (bbase + (uint32_t)(((ks) >> 2) * SLAB_BYTES) + (uint32_t)(bRow0 + (p) * 16) * 128 \
                      + (uint32_t)((((ks) & 3) * 32 + bK16) ^ xB))

    if (tid == 0)
        asm volatile("mbarrier.init.shared.b64 [%0], %1;" :: "r"(mbar), "r"(1u) : "memory");
    __syncthreads();
    if (tid == 0) {
        int rt0, ct0; decode_tile(blockIdx.x, rt0, ct0);
        issue_tile_copy(abase, mbar, rt0, ct0);
    }

    int it = 0;
    for (int idx = blockIdx.x; idx < NBLOCKS; idx += GRID_GEMM, ++it) {
        int rt, ct; decode_tile(idx, rt, ct);
        const bool diag = (rt == ct);
        const uint32_t bbase = diag ? abase : (abase + TILE_BYTES);

        MBAR_WAIT(mbar, (uint32_t)(it & 1));

        float c[2][8][4];
        #pragma unroll
        for (int mi = 0; mi < 2; mi++)
            #pragma unroll
            for (int ni = 0; ni < 8; ni++)
                #pragma unroll
                for (int e = 0; e < 4; e++) c[mi][ni][e] = 0.0f;

        // -------- software-pipelined mainloop --------
        uint32_t a[2][2][4];   // [buf][mi][frag]
        uint32_t bq[4], bn[4];
        ldsm_x4(a[0][0][0], a[0][0][1], a[0][0][2], a[0][0][3], A_AD(0));
        ldsm_x4(a[0][1][0], a[0][1][1], a[0][1][2], a[0][1][3], A_AD2(0));
        ldsm_x4(bq[0], bq[1], bq[2], bq[3], B_AD(0, 0));

        #pragma unroll
        for (int ks = 0; ks < 8; ks++) {
            const int cur = ks & 1, nxt = cur ^ 1;
            #pragma unroll
            for (int p = 0; p < 4; p++) {
                if (p < 3) {
                    ldsm_x4(bn[0], bn[1], bn[2], bn[3], B_AD(ks, p + 1));
                } else if (ks < 7) {
                    ldsm_x4(a[nxt][0][0], a[nxt][0][1], a[nxt][0][2], a[nxt][0][3], A_AD(ks + 1));
                    ldsm_x4(a[nxt][1][0], a[nxt][1][1], a[nxt][1][2], a[nxt][1][3], A_AD2(ks + 1));
                    ldsm_x4(bn[0], bn[1], bn[2], bn[3], B_AD(ks + 1, 0));
                }
                #pragma unroll
                for (int mi = 0; mi < 2; mi++) {
                    mma16816(c[mi][2*p][0],   c[mi][2*p][1],   c[mi][2*p][2],   c[mi][2*p][3],
                             a[cur][mi][0], a[cur][mi][1], a[cur][mi][2], a[cur][mi][3],
                             bq[0], bq[1]);
                    mma16816(c[mi][2*p+1][0], c[mi][2*p+1][1], c[mi][2*p+1][2], c[mi][2*p+1][3],
                             a[cur][mi][0], a[cur][mi][1], a[cur][mi][2], a[cur][mi][3],
                             bq[2], bq[3]);
                }
                bq[0] = bn[0]; bq[1] = bn[1]; bq[2] = bn[2]; bq[3] = bn[3];
            }
        }

        __syncthreads();                  // all warps done reading A/B
        if (tid == 0 && idx + GRID_GEMM < NBLOCKS) {
            int rtn, ctn; decode_tile(idx + GRID_GEMM, rtn, ctn);
            issue_tile_copy(abase, mbar, rtn, ctn);   // overlaps epilogue
        }

        // ---- epilogue: exp, diag mask, row sums + deferred col butterfly ----
        float rs[2][2];
        rs[0][0] = rs[0][1] = rs[1][0] = rs[1][1] = 0.0f;
        float cs[16];
        #pragma unroll
        for (int v = 0; v < 16; v++) cs[v] = 0.0f;

        #pragma unroll
        for (int ni = 0; ni < 8; ni++) {
            const int lc = wc * 64 + ni * 8 + 2 * q;
            #pragma unroll
            for (int mi = 0; mi < 2; mi++) {
                const int lr0 = wr * 32 + mi * 16 + g;
                const int lr1 = lr0 + 8;
                float v0 = ex2f(c[mi][ni][0] * EXP_SCALE);
                float v1 = ex2f(c[mi][ni][1] * EXP_SCALE);
                float v2 = ex2f(c[mi][ni][2] * EXP_SCALE);
                float v3 = ex2f(c[mi][ni][3] * EXP_SCALE);
                if (diag) {
                    if (lr0 == lc)     v0 = 0.0f;
                    if (lr0 == lc + 1) v1 = 0.0f;
                    if (lr1 == lc)     v2 = 0.0f;
                    if (lr1 == lc + 1) v3 = 0.0f;
                }
                rs[mi][0] += v0 + v1;
                rs[mi][1] += v2 + v3;
                cs[2 * ni]     += v0 + v2;
                cs[2 * ni + 1] += v1 + v3;
            }
        }

        if (!diag) {
            #pragma unroll
            for (int i = 0; i < 8; i++) {
                float keep = (lane & 4) ? cs[i + 8] : cs[i];
                float give = (lane & 4) ? cs[i] : cs[i + 8];
                cs[i] = keep + __shfl_xor_sync(0xffffffffu, give, 4);
            }
            #pragma unroll
            for (int i = 0; i < 4; i++) {
                float keep = (lane & 8) ? cs[i + 4] : cs[i];
                float give = (lane & 8) ? cs[i] : cs[i + 4];
                cs[i] = keep + __shfl_xor_sync(0xffffffffu, give, 8);
            }
            #pragma unroll
            for (int i = 0; i < 2; i++) {
                float keep = (lane & 16) ? cs[i + 2] : cs[i];
                float give = (lane & 16) ? cs[i] : cs[i + 2];
                cs[i] = keep + __shfl_xor_sync(0xffffffffu, give, 16);
            }
            const int v0 = ((lane & 4) ? 8 : 0) + ((lane & 8) ? 4 : 0) + ((lane & 16) ? 2 : 0);
            const int col0 = wc * 64 + (v0 >> 1) * 8 + 2 * q;
            scol[wr][col0]     = cs[0];
            scol[wr][col0 + 1] = cs[1];
        }

        #pragma unroll
        for (int mi = 0; mi < 2; mi++) {
            rs[mi][0] += __shfl_xor_sync(0xffffffffu, rs[mi][0], 1);
            rs[mi][0] += __shfl_xor_sync(0xffffffffu, rs[mi][0], 2);
            rs[mi][1] += __shfl_xor_sync(0xffffffffu, rs[mi][1], 1);
            rs[mi][1] += __shfl_xor_sync(0xffffffffu, rs[mi][1], 2);
        }
        if (q == 0) {
            #pragma unroll
            for (int mi = 0; mi < 2; mi++) {
                const int lr = wr * 32 + mi * 16 + g;
                srow[wc][lr]     = rs[mi][0];
                srow[wc][lr + 8] = rs[mi][1];
            }
        }
        __syncthreads();

        if (tid < 128) {
            float v = srow[0][tid] + srow[1][tid];
            g_partial[(rt * 128 + tid) * NTILES + ct] = v;
        } else if (!diag) {
            const int cI = tid - 128;
            float v = scol[0][cI] + scol[1][cI] + scol[2][cI] + scol[3][cI];
            g_partial[(ct * 128 + cI) * NTILES + rt] = v;
        }
    }
#undef A_AD
#undef A_AD2
#undef B_AD
}

// ---------------------------------------------------------------------------
// K3: per-row log-sum + positives + last-block finalize. grid 64 x 128.
__global__ void k_reduce(float* __restrict__ out) {
    int tid  = threadIdx.x;
    int lane = tid & 31, wid = tid >> 5;
    __shared__ float sred1[4], sred2[4];

    // part 1: log of row sums (one row per thread)
    int row = blockIdx.x * 128 + tid;
    const float4* p = reinterpret_cast<const float4*>(g_partial + row * NTILES);
    float s = 0.0f;
    #pragma unroll
    for (int i = 0; i < 16; i++) {
        float4 v = p[i];
        s += (v.x + v.y) + (v.z + v.w);
    }
    float lg = logf(s);
    #pragma unroll
    for (int o = 16; o > 0; o >>= 1) lg += __shfl_xor_sync(0xffffffffu, lg, o);
    if (lane == 0) sred1[wid] = lg;

    // part 2: positives — 64 pairs per block, 2 threads per pair
    int pr = blockIdx.x * 64 + (tid >> 1);
    int h  = tid & 1;
    const float4* pa = reinterpret_cast<const float4*>(g_zf + pr * DDIM + h * 64);
    const float4* pb = reinterpret_cast<const float4*>(g_zf + (pr + BROWS) * DDIM + h * 64);
    float d = 0.0f;
    #pragma unroll
    for (int e = 0; e < 16; e++) {
        float4 va = pa[e], vb = pb[e];
        d += va.x * vb.x + va.y * vb.y + va.z * vb.z + va.w * vb.w;
    }
    d += __shfl_xor_sync(0xffffffffu, d, 1);
    float ps = (h == 0) ? d : 0.0f;
    #pragma unroll
    for (int o = 16; o > 0; o >>= 1) ps += __shfl_xor_sync(0xffffffffu, ps, o);
    if (lane == 0) sred2[wid] = ps;

    __syncthreads();
    if (tid == 0) {
        float t1 = sred1[0] + sred1[1] + sred1[2] + sred1[3];
        float t2 = sred2[0] + sred2[1] + sred2[2] + sred2[3];
        g_ploss[blockIdx.x]  = t1;
        g_possum[blockIdx.x] = t2;
        __threadfence();
        int old = atomicAdd(&g_ctr, 1);
        if (old == 63) {                       // last block finalizes
            g_ctr = 0;                         // reset for next graph replay
            volatile float* pl = g_ploss;
            volatile float* pp = g_possum;
            float acc = 0.0f;
            for (int i = 0; i < 64; i++) acc += pl[i] - 20.0f * pp[i];
            out[0] = acc / (float)TWOB;
        }
    }
}

// ---------------------------------------------------------------------------
extern "C" void kernel_launch(void* const* d_in, const int* in_sizes, int n_in,
                              void* d_out, int out_size) {
    const float* xi = (const float*)d_in[0];
    const float* xj = (const float*)d_in[1];
    float* out = (float*)d_out;

    k_normalize<<<TWOB / 8, 256>>>(xi, xj);

    const int smem_bytes = 2 * TILE_BYTES + 1024;   // 66560 -> 2 CTAs/SM
    cudaFuncSetAttribute(k_gemm_exp, cudaFuncAttributeMaxDynamicSharedMemorySize, smem_bytes);
    k_gemm_exp<<<GRID_GEMM, 256, smem_bytes>>>();

    k_reduce<<<64, 128>>>(out);
}

// round 11
// speedup vs baseline: 1.4045x; 1.0049x over previous
#include <cuda_runtime.h>
#include <cuda_bf16.h>
#include <cstdint>

// ---------------------------------------------------------------------------
// SimCLR (NT-Xent) loss, B=4096, D=128, T=0.1 — symmetric triangular GEMM.
// Persistent CTAs with row-chunked tile assignment: A tile cached in smem per
// chunk, B tiles streamed through a 2-slot double buffer (copy i+1 issued
// before mainloop i). Fused exp+row/col sums; reduce+finalize fused.
// ---------------------------------------------------------------------------

#define BROWS    4096
#define TWOB     8192
#define DDIM     128
#define NTILES   64
#define NBLOCKS  (NTILES * (NTILES + 1) / 2)   // 2080
#define TILE_BYTES 32768
#define SLAB_BYTES 16384
#define GRID_GEMM  296                         // 2 per SM
#define EXP_SCALE 14.4269504089f               // 10 * log2(e)

__device__ __nv_bfloat16 g_zb[TWOB * DDIM];    // swizzled tile layout
__device__ float         g_zf[TWOB * DDIM];    // row-major fp32 (positives)
__device__ float         g_partial[TWOB * NTILES];  // [row][tile]
__device__ float         g_ploss[64];
__device__ float         g_possum[64];
__device__ int           g_ctr = 0;

// ---------------------------------------------------------------------------
__device__ __forceinline__ float ex2f(float x) {
    float y;
    asm("ex2.approx.ftz.f32 %0, %1;" : "=f"(y) : "f"(x));
    return y;
}

__device__ __forceinline__ void mma16816(float& c0, float& c1, float& c2, float& c3,
                                         uint32_t a0, uint32_t a1, uint32_t a2, uint32_t a3,
                                         uint32_t b0, uint32_t b1) {
    asm volatile(
        "mma.sync.aligned.m16n8k16.row.col.f32.bf16.bf16.f32 "
        "{%0,%1,%2,%3}, {%4,%5,%6,%7}, {%8,%9}, {%0,%1,%2,%3};"
        : "+f"(c0), "+f"(c1), "+f"(c2), "+f"(c3)
        : "r"(a0), "r"(a1), "r"(a2), "r"(a3), "r"(b0), "r"(b1));
}

__device__ __forceinline__ void ldsm_x4(uint32_t& r0, uint32_t& r1, uint32_t& r2, uint32_t& r3,
                                        uint32_t saddr) {
    asm volatile("ldmatrix.sync.aligned.m8n8.x4.shared.b16 {%0,%1,%2,%3}, [%4];"
                 : "=r"(r0), "=r"(r1), "=r"(r2), "=r"(r3) : "r"(saddr));
}

#define MBAR_WAIT(m, ph) do {                                                  \
    uint32_t _done;                                                            \
    asm volatile("{\n\t.reg .pred p;\n\t"                                      \
        "mbarrier.try_wait.parity.acquire.cta.shared::cta.b64 p, [%1], %2;\n\t"\
        "selp.b32 %0, 1, 0, p;\n\t}"                                           \
        : "=r"(_done) : "r"(m), "r"(ph) : "memory");                           \
    if (!_done) {                                                              \
        asm volatile("{\n\t.reg .pred P1;\n\t"                                 \
        "WL_%=:\n\t"                                                           \
        "mbarrier.try_wait.parity.acquire.cta.shared::cta.b64 P1, [%0], %1, 0x989680;\n\t" \
        "@P1 bra.uni WD_%=;\n\t"                                               \
        "bra.uni WL_%=;\n\t"                                                   \
        "WD_%=:\n\t}" :: "r"(m), "r"(ph) : "memory");                          \
    }                                                                          \
} while (0)

__device__ __forceinline__ void decode_tile(int idx, int& rt, int& ct) {
    int rem = idx, r = 0;
    while (rem >= NTILES - r) { rem -= NTILES - r; r++; }
    rt = r; ct = r + rem;
}

// one 32KB tile copy with its own mbarrier
__device__ __forceinline__ void issue_copy(uint32_t dst, uint32_t mbar, int tile) {
    asm volatile("mbarrier.arrive.expect_tx.shared.b64 _, [%0], %1;"
                 :: "r"(mbar), "r"((uint32_t)TILE_BYTES) : "memory");
    const char* src = reinterpret_cast<const char*>(g_zb) + (size_t)tile * TILE_BYTES;
    asm volatile("cp.async.bulk.shared::cta.global.mbarrier::complete_tx::bytes "
                 "[%0], [%1], %2, [%3];"
                 :: "r"(dst), "l"(src), "r"((uint32_t)TILE_BYTES), "r"(mbar) : "memory");
}

// ---------------------------------------------------------------------------
// K1: normalize, 2 rows per warp (MLP=2); write g_zb tile-local SW128 layout.
__global__ void k_normalize(const float* __restrict__ xi, const float* __restrict__ xj) {
    int wid  = threadIdx.x >> 5;
    int lane = threadIdx.x & 31;
    int row0 = blockIdx.x * 16 + wid * 2;

    #pragma unroll
    for (int rr = 0; rr < 2; rr++) {
        // interleaving handled by ILP below; load both first
    }
    int rA = row0, rB = row0 + 1;
    const float* sA = (rA < BROWS) ? (xi + rA * DDIM) : (xj + (rA - BROWS) * DDIM);
    const float* sB = (rB < BROWS) ? (xi + rB * DDIM) : (xj + (rB - BROWS) * DDIM);
    float4 vA = *reinterpret_cast<const float4*>(sA + lane * 4);
    float4 vB = *reinterpret_cast<const float4*>(sB + lane * 4);
    float ssA = vA.x * vA.x + vA.y * vA.y + vA.z * vA.z + vA.w * vA.w;
    float ssB = vB.x * vB.x + vB.y * vB.y + vB.z * vB.z + vB.w * vB.w;
    #pragma unroll
    for (int o = 16; o > 0; o >>= 1) {
        ssA += __shfl_xor_sync(0xffffffffu, ssA, o);
        ssB += __shfl_xor_sync(0xffffffffu, ssB, o);
    }
    float invA = 1.0f / fmaxf(sqrtf(ssA), 1e-12f);
    float invB = 1.0f / fmaxf(sqrtf(ssB), 1e-12f);

    #pragma unroll
    for (int rr = 0; rr < 2; rr++) {
        int row = row0 + rr;
        float4 v = rr ? vB : vA;
        float inv = rr ? invB : invA;
        float4 z;
        z.x = v.x * inv; z.y = v.y * inv; z.z = v.z * inv; z.w = v.w * inv;
        *reinterpret_cast<float4*>(g_zf + row * DDIM + lane * 4) = z;
        __nv_bfloat162 b0 = __floats2bfloat162_rn(z.x, z.y);
        __nv_bfloat162 b1 = __floats2bfloat162_rn(z.z, z.w);
        uint2 pk = make_uint2(*reinterpret_cast<uint32_t*>(&b0),
                              *reinterpret_cast<uint32_t*>(&b1));
        char* dst = reinterpret_cast<char*>(g_zb)
                  + (row >> 7) * TILE_BYTES + (lane >> 4) * SLAB_BYTES;
        uint32_t wb = (uint32_t)((row & 127) * 128 + (lane & 15) * 8);
        wb ^= (wb >> 3) & 0x70;                   // SW128 swizzle
        *reinterpret_cast<uint2*>(dst + wb) = pk;
    }
}

// ---------------------------------------------------------------------------
// K2: persistent triangular fused GEMM + exp + row/col sums.
// 8 warps = 4(m) x 2(n), warp tile 32x64, software-pipelined ldmatrix.
// A cached per chunk; B double-buffered, copy issued one tile ahead.
__global__ __launch_bounds__(256, 2) void k_gemm_exp(void) {
    extern __shared__ char dsm[];
    __shared__ __align__(8) uint64_t s_mbars[3];
    __shared__ float srow[2][128];
    __shared__ float scol[4][128];

    const int tid  = threadIdx.x;
    const int lane = tid & 31;
    const int wid  = tid >> 5;
    const int g    = lane >> 2;
    const int q    = lane & 3;
    const int wr   = wid & 3;        // warp m-row 0..3
    const int wc   = wid >> 2;       // warp n-col 0..1

    const uint32_t dbase = (uint32_t)__cvta_generic_to_shared(dsm);
    const uint32_t abase = (dbase + 1023u) & ~1023u;     // A: 32KB
    const uint32_t bb0   = abase + TILE_BYTES;           // B slot 0
    const uint32_t bb1   = bb0 + TILE_BYTES;             // B slot 1
    const uint32_t mbarA  = (uint32_t)__cvta_generic_to_shared(&s_mbars[0]);
    const uint32_t mbarB0 = mbarA + 8;
    const uint32_t mbarB1 = mbarA + 16;

    // ldmatrix lane geometry
    const int sub = lane >> 3;
    const int li  = lane & 7;
    const int aRow0 = wr * 32 + li + ((sub & 1) << 3);
    const int aK16  = (sub >> 1) << 4;
    const int xA    = (aRow0 & 7) << 4;
    const int bRow0 = wc * 64 + li + ((sub >> 1) << 3);
    const int bK16  = (sub & 1) << 4;
    const int xB    = (bRow0 & 7) << 4;

#define A_AD(ks)     (abase + (uint32_t)(((ks) >> 2) * SLAB_BYTES) + (uint32_t)aRow0 * 128 \
                      + (uint32_t)((((ks) & 3) * 32 + aK16) ^ xA))
#define A_AD2(ks)    (abase + (uint32_t)(((ks) >> 2) * SLAB_BYTES) + (uint32_t)(aRow0 + 16) * 128 \
                      + (uint32_t)((((ks) & 3) * 32 + aK16) ^ xA))
#define B_AD(ks, p)  (bbase + (uint32_t)(((ks) >> 2) * SLAB_BYTES) + (uint32_t)(bRow0 + (p) * 16) * 128 \
                      + (uint32_t)((((ks) & 3) * 32 + bK16) ^ xB))

    // chunk assignment: first 8 CTAs take 8 tiles, rest 7  (8*8+288*7 = 2080)
    const int bid   = blockIdx.x;
    const int start = bid * 7 + min(bid, 8);
    const int count = 7 + (bid < 8 ? 1 : 0);

    if (tid == 0) {
        asm volatile("mbarrier.init.shared.b64 [%0], %1;" :: "r"(mbarA),  "r"(1u) : "memory");
        asm volatile("mbarrier.init.shared.b64 [%0], %1;" :: "r"(mbarB0), "r"(1u) : "memory");
        asm volatile("mbarrier.init.shared.b64 [%0], %1;" :: "r"(mbarB1), "r"(1u) : "memory");
    }
    __syncthreads();

    int rt0, ct0; decode_tile(start, rt0, ct0);
    if (tid == 0) {
        issue_copy(abase, mbarA, rt0);
        issue_copy(bb0, mbarB0, ct0);
    }
    int rtPrev = rt0;
    uint32_t phA = 0, phB0 = 0, phB1 = 0;
    bool aPend = true;
    int s = 0;

    for (int i = 0; i < count; i++) {
        const int idx = start + i;
        int rt, ct; decode_tile(idx, rt, ct);
        const bool diag = (rt == ct);
        const uint32_t bbase = s ? bb1 : bb0;

        if (i > 0 && rt != rtPrev) {      // rare A reload (prev mainloop done)
            if (tid == 0) issue_copy(abase, mbarA, rt);
            aPend = true;
            rtPrev = rt;
        }
        if (i + 1 < count) {              // stream next B into the other slot
            int rtn, ctn; decode_tile(idx + 1, rtn, ctn);
            if (tid == 0) issue_copy(s ? bb0 : bb1, s ? mbarB0 : mbarB1, ctn);
        }

        MBAR_WAIT(s ? mbarB1 : mbarB0, s ? phB1 : phB0);
        if (s) phB1 ^= 1; else phB0 ^= 1;
        if (aPend) { MBAR_WAIT(mbarA, phA); phA ^= 1; aPend = false; }

        float c[2][8][4];
        #pragma unroll
        for (int mi = 0; mi < 2; mi++)
            #pragma unroll
            for (int ni = 0; ni < 8; ni++)
                #pragma unroll
                for (int e = 0; e < 4; e++) c[mi][ni][e] = 0.0f;

        // -------- software-pipelined mainloop --------
        uint32_t a[2][2][4];
        uint32_t bq[4], bn[4];
        ldsm_x4(a[0][0][0], a[0][0][1], a[0][0][2], a[0][0][3], A_AD(0));
        ldsm_x4(a[0][1][0], a[0][1][1], a[0][1][2], a[0][1][3], A_AD2(0));
        ldsm_x4(bq[0], bq[1], bq[2], bq[3], B_AD(0, 0));

        #pragma unroll
        for (int ks = 0; ks < 8; ks++) {
            const int cur = ks & 1, nxt = cur ^ 1;
            #pragma unroll
            for (int p = 0; p < 4; p++) {
                if (p < 3) {
                    ldsm_x4(bn[0], bn[1], bn[2], bn[3], B_AD(ks, p + 1));
                } else if (ks < 7) {
                    ldsm_x4(a[nxt][0][0], a[nxt][0][1], a[nxt][0][2], a[nxt][0][3], A_AD(ks + 1));
                    ldsm_x4(a[nxt][1][0], a[nxt][1][1], a[nxt][1][2], a[nxt][1][3], A_AD2(ks + 1));
                    ldsm_x4(bn[0], bn[1], bn[2], bn[3], B_AD(ks + 1, 0));
                }
                #pragma unroll
                for (int mi = 0; mi < 2; mi++) {
                    mma16816(c[mi][2*p][0],   c[mi][2*p][1],   c[mi][2*p][2],   c[mi][2*p][3],
                             a[cur][mi][0], a[cur][mi][1], a[cur][mi][2], a[cur][mi][3],
                             bq[0], bq[1]);
                    mma16816(c[mi][2*p+1][0], c[mi][2*p+1][1], c[mi][2*p+1][2], c[mi][2*p+1][3],
                             a[cur][mi][0], a[cur][mi][1], a[cur][mi][2], a[cur][mi][3],
                             bq[2], bq[3]);
                }
                bq[0] = bn[0]; bq[1] = bn[1]; bq[2] = bn[2]; bq[3] = bn[3];
            }
        }

        __syncthreads();                  // all warps done reading this B slot

        // ---- epilogue: exp, diag mask, row sums + deferred col butterfly ----
        float rs[2][2];
        rs[0][0] = rs[0][1] = rs[1][0] = rs[1][1] = 0.0f;
        float cs[16];
        #pragma unroll
        for (int v = 0; v < 16; v++) cs[v] = 0.0f;

        #pragma unroll
        for (int ni = 0; ni < 8; ni++) {
            const int lc = wc * 64 + ni * 8 + 2 * q;
            #pragma unroll
            for (int mi = 0; mi < 2; mi++) {
                const int lr0 = wr * 32 + mi * 16 + g;
                const int lr1 = lr0 + 8;
                float v0 = ex2f(c[mi][ni][0] * EXP_SCALE);
                float v1 = ex2f(c[mi][ni][1] * EXP_SCALE);
                float v2 = ex2f(c[mi][ni][2] * EXP_SCALE);
                float v3 = ex2f(c[mi][ni][3] * EXP_SCALE);
                if (diag) {
                    if (lr0 == lc)     v0 = 0.0f;
                    if (lr0 == lc + 1) v1 = 0.0f;
                    if (lr1 == lc)     v2 = 0.0f;
                    if (lr1 == lc + 1) v3 = 0.0f;
                }
                rs[mi][0] += v0 + v1;
                rs[mi][1] += v2 + v3;
                cs[2 * ni]     += v0 + v2;
                cs[2 * ni + 1] += v1 + v3;
            }
        }

        if (!diag) {
            #pragma unroll
            for (int i2 = 0; i2 < 8; i2++) {
                float keep = (lane & 4) ? cs[i2 + 8] : cs[i2];
                float give = (lane & 4) ? cs[i2] : cs[i2 + 8];
                cs[i2] = keep + __shfl_xor_sync(0xffffffffu, give, 4);
            }
            #pragma unroll
            for (int i2 = 0; i2 < 4; i2++) {
                float keep = (lane & 8) ? cs[i2 + 4] : cs[i2];
                float give = (lane & 8) ? cs[i2] : cs[i2 + 4];
                cs[i2] = keep + __shfl_xor_sync(0xffffffffu, give, 8);
            }
            #pragma unroll
            for (int i2 = 0; i2 < 2; i2++) {
                float keep = (lane & 16) ? cs[i2 + 2] : cs[i2];
                float give = (lane & 16) ? cs[i2] : cs[i2 + 2];
                cs[i2] = keep + __shfl_xor_sync(0xffffffffu, give, 16);
            }
            const int v0 = ((lane & 4) ? 8 : 0) + ((lane & 8) ? 4 : 0) + ((lane & 16) ? 2 : 0);
            const int col0 = wc * 64 + (v0 >> 1) * 8 + 2 * q;
            scol[wr][col0]     = cs[0];
            scol[wr][col0 + 1] = cs[1];
        }

        #pragma unroll
        for (int mi = 0; mi < 2; mi++) {
            rs[mi][0] += __shfl_xor_sync(0xffffffffu, rs[mi][0], 1);
            rs[mi][0] += __shfl_xor_sync(0xffffffffu, rs[mi][0], 2);
            rs[mi][1] += __shfl_xor_sync(0xffffffffu, rs[mi][1], 1);
            rs[mi][1] += __shfl_xor_sync(0xffffffffu, rs[mi][1], 2);
        }
        if (q == 0) {
            #pragma unroll
            for (int mi = 0; mi < 2; mi++) {
                const int lr = wr * 32 + mi * 16 + g;
                srow[wc][lr]     = rs[mi][0];
                srow[wc][lr + 8] = rs[mi][1];
            }
        }
        __syncthreads();

        if (tid < 128) {
            float v = srow[0][tid] + srow[1][tid];
            g_partial[(rt * 128 + tid) * NTILES + ct] = v;
        } else if (!diag) {
            const int cI = tid - 128;
            float v = scol[0][cI] + scol[1][cI] + scol[2][cI] + scol[3][cI];
            g_partial[(ct * 128 + cI) * NTILES + rt] = v;
        }
        s ^= 1;
    }
#undef A_AD
#undef A_AD2
#undef B_AD
}

// ---------------------------------------------------------------------------
// K3: per-row log-sum + positives + last-block finalize. grid 64 x 128.
__global__ void k_reduce(float* __restrict__ out) {
    int tid  = threadIdx.x;
    int lane = tid & 31, wid = tid >> 5;
    __shared__ float sred1[4], sred2[4];

    int row = blockIdx.x * 128 + tid;
    const float4* p = reinterpret_cast<const float4*>(g_partial + row * NTILES);
    float s = 0.0f;
    #pragma unroll
    for (int i = 0; i < 16; i++) {
        float4 v = p[i];
        s += (v.x + v.y) + (v.z + v.w);
    }
    float lg = logf(s);
    #pragma unroll
    for (int o = 16; o > 0; o >>= 1) lg += __shfl_xor_sync(0xffffffffu, lg, o);
    if (lane == 0) sred1[wid] = lg;

    int pr = blockIdx.x * 64 + (tid >> 1);
    int h  = tid & 1;
    const float4* pa = reinterpret_cast<const float4*>(g_zf + pr * DDIM + h * 64);
    const float4* pb = reinterpret_cast<const float4*>(g_zf + (pr + BROWS) * DDIM + h * 64);
    float d = 0.0f;
    #pragma unroll
    for (int e = 0; e < 16; e++) {
        float4 va = pa[e], vb = pb[e];
        d += va.x * vb.x + va.y * vb.y + va.z * vb.z + va.w * vb.w;
    }
    d += __shfl_xor_sync(0xffffffffu, d, 1);
    float ps = (h == 0) ? d : 0.0f;
    #pragma unroll
    for (int o = 16; o > 0; o >>= 1) ps += __shfl_xor_sync(0xffffffffu, ps, o);
    if (lane == 0) sred2[wid] = ps;

    __syncthreads();
    if (tid == 0) {
        float t1 = sred1[0] + sred1[1] + sred1[2] + sred1[3];
        float t2 = sred2[0] + sred2[1] + sred2[2] + sred2[3];
        g_ploss[blockIdx.x]  = t1;
        g_possum[blockIdx.x] = t2;
        __threadfence();
        int old = atomicAdd(&g_ctr, 1);
        if (old == 63) {
            g_ctr = 0;                         // reset for next graph replay
            volatile float* pl = g_ploss;
            volatile float* pp = g_possum;
            float acc = 0.0f;
            for (int i = 0; i < 64; i++) acc += pl[i] - 20.0f * pp[i];
            out[0] = acc / (float)TWOB;
        }
    }
}

// ---------------------------------------------------------------------------
extern "C" void kernel_launch(void* const* d_in, const int* in_sizes, int n_in,
                              void* d_out, int out_size) {
    const float* xi = (const float*)d_in[0];
    const float* xj = (const float*)d_in[1];
    float* out = (float*)d_out;

    k_normalize<<<TWOB / 16, 256>>>(xi, xj);

    const int smem_bytes = 3 * TILE_BYTES + 1024;   // 99328 -> 2 CTAs/SM
    cudaFuncSetAttribute(k_gemm_exp, cudaFuncAttributeMaxDynamicSharedMemorySize, smem_bytes);
    k_gemm_exp<<<GRID_GEMM, 256, smem_bytes>>>();

    k_reduce<<<64, 128>>>(out);
}